// round 16
// baseline (speedup 1.0000x reference)
#include <cuda_runtime.h>
#include <cuda_bf16.h>
#include <math.h>
#include <stdint.h>

#define NTOK 4096
#define DMODEL 512
#define NEXP 8
#define HDIM 2048
#define EHDIM (NEXP * HDIM)   // 16384

// ---------------- device scratch ----------------
__device__ __align__(16) unsigned short g_xh[NTOK * DMODEL];
__device__ __align__(16) unsigned short g_xl[NTOK * DMODEL];
__device__ __align__(16) unsigned short g_wgh[EHDIM * DMODEL];   // [EH][D] transposed
__device__ __align__(16) unsigned short g_wgl[EHDIM * DMODEL];
__device__ __align__(16) unsigned short g_wuh[EHDIM * DMODEL];
__device__ __align__(16) unsigned short g_wul[EHDIM * DMODEL];
__device__ __align__(16) unsigned short g_wdh[DMODEL * HDIM];    // [D][H] transposed
__device__ __align__(16) unsigned short g_wdl[DMODEL * HDIM];
__device__ __align__(16) float  g_part[2 * NTOK * HDIM];
__device__ __align__(16) unsigned short g_ah[NTOK * HDIM];       // summed combined, split
__device__ __align__(16) unsigned short g_al[NTOK * HDIM];
__device__ int    g_cnt[NEXP];
__device__ double g_esum[NEXP];
__device__ int    g_elist[NEXP * NTOK];   // token | (slot<<16)
__device__ float  g_eprob[NEXP * NTOK];

// ---------------- helpers ----------------
__device__ __forceinline__ uint32_t smem_u32(const void* p) {
    uint32_t a;
    asm("{ .reg .u64 t; cvta.to.shared.u64 t, %1; cvt.u32.u64 %0, t; }"
        : "=r"(a) : "l"(p));
    return a;
}
__device__ __forceinline__ void cp16(uint32_t dst, const void* src) {
    asm volatile("cp.async.cg.shared.global [%0], [%1], 16;" :: "r"(dst), "l"(src));
}
#define CP_COMMIT() asm volatile("cp.async.commit_group;" ::: "memory")
#define CP_WAIT1()  asm volatile("cp.async.wait_group 1;" ::: "memory")

__device__ __forceinline__ void ldm4(uint32_t* r, uint32_t addr) {
    asm volatile("ldmatrix.sync.aligned.m8n8.x4.shared.b16 {%0,%1,%2,%3}, [%4];"
                 : "=r"(r[0]), "=r"(r[1]), "=r"(r[2]), "=r"(r[3]) : "r"(addr));
}

// m16n8k16 bf16 MMA (sm_80 baseline PTX -> tensor pipe)
__device__ __forceinline__ void mma16(float* c, const uint32_t* a, const uint32_t* b) {
    asm volatile(
        "mma.sync.aligned.m16n8k16.row.col.f32.bf16.bf16.f32 "
        "{%0,%1,%2,%3}, {%4,%5,%6,%7}, {%8,%9}, {%0,%1,%2,%3};"
        : "+f"(c[0]), "+f"(c[1]), "+f"(c[2]), "+f"(c[3])
        : "r"(a[0]), "r"(a[1]), "r"(a[2]), "r"(a[3]), "r"(b[0]), "r"(b[1]));
}

__device__ __forceinline__ void bsplit(float v, unsigned short& h, unsigned short& l) {
    __nv_bfloat16 hb = __float2bfloat16(v);
    h = __bfloat16_as_ushort(hb);
    float r = v - __bfloat162float(hb);
    l = __bfloat16_as_ushort(__float2bfloat16(r));
}

// ---------------- merged prep: x split + w_down split-transpose ----------------
// blocks [0, 2048): prep_xc (256 thr linear); blocks [2048, 3072): prep_wd (32x8 logic)
#define XC_BLOCKS 2048
__global__ void prep_x_wd(const float* __restrict__ x, const float* __restrict__ wd) {
    if (blockIdx.x < XC_BLOCKS) {
        int i = blockIdx.x * 256 + threadIdx.x;
        if (i == 0) {
#pragma unroll
            for (int e = 0; e < NEXP; e++) { g_cnt[e] = 0; g_esum[e] = 0.0; }
        }
        float4 v = reinterpret_cast<const float4*>(x)[i];
        unsigned short h0, h1, h2, h3, l0, l1, l2, l3;
        bsplit(v.x, h0, l0); bsplit(v.y, h1, l1);
        bsplit(v.z, h2, l2); bsplit(v.w, h3, l3);
        reinterpret_cast<ushort4*>(g_xh)[i] = make_ushort4(h0, h1, h2, h3);
        reinterpret_cast<ushort4*>(g_xl)[i] = make_ushort4(l0, l1, l2, l3);
    } else {
        __shared__ float t[32][33];
        int b = blockIdx.x - XC_BLOCKS;             // 0..1023
        int db = (b & 15) * 32, hb = (b >> 4) * 32; // 16 d-tiles x 64 h-tiles
        int tx = threadIdx.x & 31, ty = threadIdx.x >> 5;
#pragma unroll
        for (int i = 0; i < 4; i++) {
            t[ty + i * 8][tx] = wd[(size_t)(hb + ty + i * 8) * DMODEL + db + tx];
        }
        __syncthreads();
#pragma unroll
        for (int i = 0; i < 4; i++) {
            size_t o = (size_t)(db + ty + i * 8) * HDIM + hb + tx;
            unsigned short hh, ll;
            bsplit(t[tx][ty + i * 8], hh, ll);
            g_wdh[o] = hh; g_wdl[o] = ll;
        }
    }
}

// 64(d) x 32(h) tiles; ushort2 stores -> full 128B/warp write transactions
__global__ void prep_wgu(const float* __restrict__ wg, const float* __restrict__ wu) {
    __shared__ float tg[64][33], tu[64][33];
    int hb = blockIdx.x * 32, db = blockIdx.y * 64;
    int tx = threadIdx.x, ty = threadIdx.y;   // (32, 8)
#pragma unroll
    for (int i = 0; i < 8; i++) {
        int d = db + ty + i * 8;
        tg[ty + i * 8][tx] = wg[(size_t)d * EHDIM + hb + tx];
        tu[ty + i * 8][tx] = wu[(size_t)d * EHDIM + hb + tx];
    }
    __syncthreads();
#pragma unroll
    for (int i = 0; i < 4; i++) {
        int hh = ty + i * 8;
        size_t o = (size_t)(hb + hh) * DMODEL + db + tx * 2;
        unsigned short a0, b0, a1, b1;
        bsplit(tg[tx * 2][hh], a0, b0); bsplit(tg[tx * 2 + 1][hh], a1, b1);
        *reinterpret_cast<ushort2*>(&g_wgh[o]) = make_ushort2(a0, a1);
        *reinterpret_cast<ushort2*>(&g_wgl[o]) = make_ushort2(b0, b1);
        bsplit(tu[tx * 2][hh], a0, b0); bsplit(tu[tx * 2 + 1][hh], a1, b1);
        *reinterpret_cast<ushort2*>(&g_wuh[o]) = make_ushort2(a0, a1);
        *reinterpret_cast<ushort2*>(&g_wul[o]) = make_ushort2(b0, b1);
    }
}

// sum the two expert partials, bf16-split -> A operand of down GEMM
__global__ void convert_part() {
    int i = blockIdx.x * blockDim.x + threadIdx.x;   // over NTOK*HDIM/4
    float4 a = reinterpret_cast<const float4*>(g_part)[i];
    float4 b = reinterpret_cast<const float4*>(g_part + (size_t)NTOK * HDIM)[i];
    unsigned short h0, h1, h2, h3, l0, l1, l2, l3;
    bsplit(a.x + b.x, h0, l0); bsplit(a.y + b.y, h1, l1);
    bsplit(a.z + b.z, h2, l2); bsplit(a.w + b.w, h3, l3);
    reinterpret_cast<ushort4*>(g_ah)[i] = make_ushort4(h0, h1, h2, h3);
    reinterpret_cast<ushort4*>(g_al)[i] = make_ushort4(l0, l1, l2, l3);
}

// ---------------- router: one warp per token ----------------
__global__ void router_kernel(const float* __restrict__ x,
                              const float* __restrict__ w_router) {
    int warp = (blockIdx.x * blockDim.x + threadIdx.x) >> 5;
    int lane = threadIdx.x & 31;
    if (warp >= NTOK) return;
    int n = warp;

    float acc[NEXP];
#pragma unroll
    for (int e = 0; e < NEXP; e++) acc[e] = 0.f;
    const float* xr = x + (size_t)n * DMODEL;
    for (int d = lane; d < DMODEL; d += 32) {
        float xv = xr[d];
        const float* w = w_router + d * NEXP;
#pragma unroll
        for (int e = 0; e < NEXP; e++) acc[e] += xv * w[e];
    }
#pragma unroll
    for (int off = 16; off > 0; off >>= 1)
#pragma unroll
        for (int e = 0; e < NEXP; e++)
            acc[e] += __shfl_xor_sync(0xFFFFFFFFu, acc[e], off);

    if (lane == 0) {
        float mx = acc[0];
#pragma unroll
        for (int e = 1; e < NEXP; e++) mx = fmaxf(mx, acc[e]);
        float s = 0.f, probs[NEXP];
#pragma unroll
        for (int e = 0; e < NEXP; e++) { probs[e] = expf(acc[e] - mx); s += probs[e]; }
        float inv = 1.f / s;
#pragma unroll
        for (int e = 0; e < NEXP; e++) {
            probs[e] *= inv;
            atomicAdd(&g_esum[e], (double)probs[e]);
        }
        int i1 = 0;
#pragma unroll
        for (int e = 1; e < NEXP; e++) if (probs[e] > probs[i1]) i1 = e;
        int i2 = (i1 == 0) ? 1 : 0;
#pragma unroll
        for (int e = 0; e < NEXP; e++)
            if (e != i1 && probs[e] > probs[i2]) i2 = e;

        float p1 = probs[i1], p2 = probs[i2];
        float rn = 1.f / (p1 + p2 + 1e-10f);
        int pos1 = atomicAdd(&g_cnt[i1], 1);
        g_elist[i1 * NTOK + pos1] = n;                // slot 0
        g_eprob[i1 * NTOK + pos1] = p1 * rn;
        int pos2 = atomicAdd(&g_cnt[i2], 1);
        g_elist[i2 * NTOK + pos2] = n | (1 << 16);    // slot 1
        g_eprob[i2 * NTOK + pos2] = p2 * rn;
    }
}

// ---------------- gate/up split-bf16 GEMM (R14 verbatim: 3-stage, k16) ----------------
// 256 threads = 8 warps (wm 0..3 x wn 0..1). BM=128 tokens, BN=64 h (dual G,U).
// smem row = [hi 32B (k16) | lo 32B | pad 16B] stride 80B.
#define GQS 80
#define GSTG 20480                       // X(128*80=10240) + G(5120) + U(5120)
#define GU_X(s) ((s) * GSTG)
#define GU_G(s) ((s) * GSTG + 10240)
#define GU_U(s) ((s) * GSTG + 15360)
#define GU_META (3 * GSTG)               // 61440
#define GU_DYN  (GU_META + 1664)

__global__ __launch_bounds__(256, 2) void gateup_bf16() {
    extern __shared__ __align__(16) char smem[];
    uint32_t sb = smem_u32(smem);
    float*  sP   = reinterpret_cast<float*>(smem + GU_META);          // 128 floats
    float** sDst = reinterpret_cast<float**>(smem + GU_META + 512);   // 128 ptrs

    const int tid = threadIdx.x;
    const int e = blockIdx.z;
    const int cnt = g_cnt[e];
    const int row0 = blockIdx.x * 128;
    if (row0 >= cnt) return;
    const int h0 = blockIdx.y * 64;

    if (tid < 128) {
        int gr = row0 + tid;
        bool valid = gr < cnt;
        int ent = valid ? g_elist[e * NTOK + gr] : 0;
        int t = ent & 0xFFFF;
        int slot = (ent >> 16) & 1;
        sP[tid] = valid ? g_eprob[e * NTOK + gr] : 0.f;
        sDst[tid] = valid ? (g_part + ((size_t)slot * NTOK + t) * HDIM + h0) : (float*)0;
    }

    // cp.async: every thread does 4 ops/chunk: X rows r and r+64, G row r, U row r
    const int q = tid & 3, hilo = q >> 1, seg = q & 1;
    const int r = tid >> 2;                 // 0..63
    const unsigned short* xsrc0;
    const unsigned short* xsrc1;
    {
        int gr0 = row0 + r;
        int gr1 = row0 + r + 64;
        int e0 = (gr0 < cnt) ? g_elist[e * NTOK + gr0] : 0;
        int e1 = (gr1 < cnt) ? g_elist[e * NTOK + gr1] : 0;
        const unsigned short* base = hilo ? g_xl : g_xh;
        xsrc0 = base + (size_t)(e0 & 0xFFFF) * DMODEL + seg * 8;
        xsrc1 = base + (size_t)(e1 & 0xFFFF) * DMODEL + seg * 8;
    }
    const unsigned short* gsrc;
    const unsigned short* usrc;
    {
        size_t ro = (size_t)(e * HDIM + h0 + r) * DMODEL + seg * 8;
        gsrc = (hilo ? g_wgl : g_wgh) + ro;
        usrc = (hilo ? g_wul : g_wuh) + ro;
    }
    const uint32_t xoff0 = (uint32_t)r * GQS + hilo * 32 + seg * 16;
    const uint32_t xoff1 = (uint32_t)(r + 64) * GQS + hilo * 32 + seg * 16;
    const uint32_t woff  = (uint32_t)r * GQS + hilo * 32 + seg * 16;

    // fragment addressing (verified R6/R10/R11 mapping)
    const int warp = tid >> 5, lane = tid & 31;
    const int wm = warp & 3, wn = warp >> 2;   // wm 0..3, wn 0..1
    const int grp = lane >> 2, tig = lane & 3;
    const uint32_t aLane = (uint32_t)(((lane & 7) + (lane & 8)) * GQS + ((lane & 16) ? 16 : 0));
    const uint32_t bLane = (uint32_t)((((lane & 7) + ((lane & 16) >> 1)) * GQS) + ((lane & 8) ? 16 : 0));
    uint32_t aBase[2], bBase[2];
#pragma unroll
    for (int mt = 0; mt < 2; mt++) aBase[mt] = (uint32_t)(wm * 32 + mt * 16) * GQS + aLane;
#pragma unroll
    for (int bh = 0; bh < 2; bh++) bBase[bh] = (uint32_t)(wn * 32 + bh * 16) * GQS + bLane;

    float accG[2][4][4], accU[2][4][4];   // [mt][bh*2+nt][4]
#pragma unroll
    for (int mt = 0; mt < 2; mt++)
#pragma unroll
        for (int j = 0; j < 4; j++)
#pragma unroll
            for (int k = 0; k < 4; k++) { accG[mt][j][k] = 0.f; accU[mt][j][k] = 0.f; }

    // prologue: stages 0,1
#pragma unroll
    for (int c = 0; c < 2; c++) {
        cp16(sb + GU_X(c) + xoff0, xsrc0 + c * 16);
        cp16(sb + GU_X(c) + xoff1, xsrc1 + c * 16);
        cp16(sb + GU_G(c) + woff, gsrc + c * 16);
        cp16(sb + GU_U(c) + woff, usrc + c * 16);
        CP_COMMIT();
    }

    const int NCH = DMODEL / 16;   // 32
    for (int c = 0; c < NCH; c++) {
        int s = c % 3;
        CP_WAIT1();
        __syncthreads();
        if (c + 2 < NCH) {
            int s2 = (c + 2) % 3;
            int k0 = (c + 2) * 16;
            cp16(sb + GU_X(s2) + xoff0, xsrc0 + k0);
            cp16(sb + GU_X(s2) + xoff1, xsrc1 + k0);
            cp16(sb + GU_G(s2) + woff, gsrc + k0);
            cp16(sb + GU_U(s2) + woff, usrc + k0);
        }
        CP_COMMIT();   // uniform group counting

        uint32_t xb = sb + GU_X(s), gb = sb + GU_G(s), ub = sb + GU_U(s);
        uint32_t ah[2][4], al[2][4];
        ldm4(ah[0], xb + aBase[0]); ldm4(al[0], xb + aBase[0] + 32);
        ldm4(ah[1], xb + aBase[1]); ldm4(al[1], xb + aBase[1] + 32);
        {
            uint32_t bH[2][4], bL[2][4];
            ldm4(bH[0], gb + bBase[0]); ldm4(bL[0], gb + bBase[0] + 32);
            ldm4(bH[1], gb + bBase[1]); ldm4(bL[1], gb + bBase[1] + 32);
#pragma unroll
            for (int mt = 0; mt < 2; mt++)
#pragma unroll
                for (int bh = 0; bh < 2; bh++)
#pragma unroll
                    for (int nt = 0; nt < 2; nt++) {
                        float* acc = accG[mt][bh * 2 + nt];
                        mma16(acc, ah[mt], bH[bh] + nt * 2);
                        mma16(acc, ah[mt], bL[bh] + nt * 2);
                        mma16(acc, al[mt], bH[bh] + nt * 2);
                    }
        }
        {
            uint32_t bH[2][4], bL[2][4];
            ldm4(bH[0], ub + bBase[0]); ldm4(bL[0], ub + bBase[0] + 32);
            ldm4(bH[1], ub + bBase[1]); ldm4(bL[1], ub + bBase[1] + 32);
#pragma unroll
            for (int mt = 0; mt < 2; mt++)
#pragma unroll
                for (int bh = 0; bh < 2; bh++)
#pragma unroll
                    for (int nt = 0; nt < 2; nt++) {
                        float* acc = accU[mt][bh * 2 + nt];
                        mma16(acc, ah[mt], bH[bh] + nt * 2);
                        mma16(acc, ah[mt], bL[bh] + nt * 2);
                        mma16(acc, al[mt], bH[bh] + nt * 2);
                    }
        }
    }

    // epilogue: p * silu(g) * u
#pragma unroll
    for (int mt = 0; mt < 2; mt++) {
        int r0 = wm * 32 + mt * 16 + grp;
        int r1 = r0 + 8;
        float p0 = sP[r0], p1 = sP[r1];
        float* d0 = sDst[r0];
        float* d1 = sDst[r1];
#pragma unroll
        for (int bh = 0; bh < 2; bh++)
#pragma unroll
            for (int nt = 0; nt < 2; nt++) {
                int co = wn * 32 + bh * 16 + nt * 8 + tig * 2;
                const float* aG = accG[mt][bh * 2 + nt];
                const float* aU = accU[mt][bh * 2 + nt];
                if (d0) {
                    float g0 = aG[0], u0 = aU[0];
                    float g1 = aG[1], u1 = aU[1];
                    float2 v;
                    v.x = p0 * (g0 / (1.f + __expf(-g0))) * u0;
                    v.y = p0 * (g1 / (1.f + __expf(-g1))) * u1;
                    *reinterpret_cast<float2*>(d0 + co) = v;
                }
                if (d1) {
                    float g2 = aG[2], u2 = aU[2];
                    float g3 = aG[3], u3 = aU[3];
                    float2 v;
                    v.x = p1 * (g2 / (1.f + __expf(-g2))) * u2;
                    v.y = p1 * (g3 / (1.f + __expf(-g3))) * u3;
                    *reinterpret_cast<float2*>(d1 + co) = v;
                }
            }
    }
}

// ---------------- down split-bf16 GEMM (R14 verbatim + fused lbloss) ----------------
// 256 threads = 8 warps (wm4 x wn2). BM=128 tokens, BN=64 d-cols, K=2048.
#define DSTG 15360
#define DN_A(s) ((s) * DSTG)
#define DN_B(s) ((s) * DSTG + 10240)
#define DN_DYN  (3 * DSTG)               // 46080

__global__ __launch_bounds__(256, 2) void down_bf16(float* __restrict__ out,
                                                    float* __restrict__ out_scalar) {
    extern __shared__ __align__(16) char smem[];
    uint32_t sb = smem_u32(smem);

    const int tid = threadIdx.x;
    const int row0 = blockIdx.x * 128;
    const int c0 = blockIdx.y * 64;

    // fused lb-loss (esum final since router; disjoint output element)
    if (blockIdx.x == 0 && blockIdx.y == 0 && tid == 0) {
        double lb = 0.0;
#pragma unroll
        for (int e = 0; e < NEXP; e++) {
            double m = g_esum[e] / (double)NTOK;
            lb += m * log(m * (double)NEXP + 1e-10);
        }
        out_scalar[0] = (float)((double)NEXP * lb);
    }

    const int q = tid & 3, hilo = q >> 1, seg = q & 1;
    const int r = tid >> 2;                 // 0..63
    const unsigned short* abase = hilo ? g_al : g_ah;
    const unsigned short* asrc0 = abase + (size_t)(row0 + r) * HDIM + seg * 8;
    const unsigned short* asrc1 = abase + (size_t)(row0 + r + 64) * HDIM + seg * 8;
    const unsigned short* bsrc =
        (hilo ? g_wdl : g_wdh) + (size_t)(c0 + r) * HDIM + seg * 8;
    const uint32_t aoff0 = (uint32_t)r * GQS + hilo * 32 + seg * 16;
    const uint32_t aoff1 = (uint32_t)(r + 64) * GQS + hilo * 32 + seg * 16;
    const uint32_t boff  = (uint32_t)r * GQS + hilo * 32 + seg * 16;

    const int warp = tid >> 5, lane = tid & 31;
    const int wm = warp & 3, wn = warp >> 2;
    const int grp = lane >> 2, tig = lane & 3;
    const uint32_t aLane = (uint32_t)(((lane & 7) + (lane & 8)) * GQS + ((lane & 16) ? 16 : 0));
    const uint32_t bLane = (uint32_t)((((lane & 7) + ((lane & 16) >> 1)) * GQS) + ((lane & 8) ? 16 : 0));
    uint32_t aBase[2], bBase[2];
#pragma unroll
    for (int mt = 0; mt < 2; mt++) aBase[mt] = (uint32_t)(wm * 32 + mt * 16) * GQS + aLane;
#pragma unroll
    for (int bh = 0; bh < 2; bh++) bBase[bh] = (uint32_t)(wn * 32 + bh * 16) * GQS + bLane;

    float acc[2][4][4];
#pragma unroll
    for (int mt = 0; mt < 2; mt++)
#pragma unroll
        for (int j = 0; j < 4; j++)
#pragma unroll
            for (int k = 0; k < 4; k++) acc[mt][j][k] = 0.f;

#pragma unroll
    for (int c = 0; c < 2; c++) {
        int k0 = c * 16;
        cp16(sb + DN_A(c) + aoff0, asrc0 + k0);
        cp16(sb + DN_A(c) + aoff1, asrc1 + k0);
        cp16(sb + DN_B(c) + boff,  bsrc + k0);
        CP_COMMIT();
    }

    const int NCH = HDIM / 16;   // 128
    for (int c = 0; c < NCH; c++) {
        int s = c % 3;
        CP_WAIT1();
        __syncthreads();
        if (c + 2 < NCH) {
            int s2 = (c + 2) % 3;
            int k0 = (c + 2) * 16;
            cp16(sb + DN_A(s2) + aoff0, asrc0 + k0);
            cp16(sb + DN_A(s2) + aoff1, asrc1 + k0);
            cp16(sb + DN_B(s2) + boff,  bsrc + k0);
        }
        CP_COMMIT();

        uint32_t ab = sb + DN_A(s), bb = sb + DN_B(s);
        uint32_t ah[2][4], al[2][4], bH[2][4], bL[2][4];
        ldm4(ah[0], ab + aBase[0]); ldm4(al[0], ab + aBase[0] + 32);
        ldm4(ah[1], ab + aBase[1]); ldm4(al[1], ab + aBase[1] + 32);
        ldm4(bH[0], bb + bBase[0]); ldm4(bL[0], bb + bBase[0] + 32);
        ldm4(bH[1], bb + bBase[1]); ldm4(bL[1], bb + bBase[1] + 32);

#pragma unroll
        for (int mt = 0; mt < 2; mt++)
#pragma unroll
            for (int bh = 0; bh < 2; bh++)
#pragma unroll
                for (int nt = 0; nt < 2; nt++) {
                    float* a = acc[mt][bh * 2 + nt];
                    mma16(a, ah[mt], bH[bh] + nt * 2);
                    mma16(a, ah[mt], bL[bh] + nt * 2);
                    mma16(a, al[mt], bH[bh] + nt * 2);
                }
    }

    // epilogue
#pragma unroll
    for (int mt = 0; mt < 2; mt++) {
        int r0 = row0 + wm * 32 + mt * 16 + grp;
        int r1 = r0 + 8;
#pragma unroll
        for (int bh = 0; bh < 2; bh++)
#pragma unroll
            for (int nt = 0; nt < 2; nt++) {
                int co = c0 + wn * 32 + bh * 16 + nt * 8 + tig * 2;
                const float* a = acc[mt][bh * 2 + nt];
                *reinterpret_cast<float2*>(out + (size_t)r0 * DMODEL + co) =
                    make_float2(a[0], a[1]);
                *reinterpret_cast<float2*>(out + (size_t)r1 * DMODEL + co) =
                    make_float2(a[2], a[3]);
            }
    }
}

// ---------------- launch ----------------
extern "C" void kernel_launch(void* const* d_in, const int* in_sizes, int n_in,
                              void* d_out, int out_size) {
    const float* x        = (const float*)d_in[0];
    const float* w_router = (const float*)d_in[1];
    const float* w_gate   = (const float*)d_in[2];
    const float* w_up     = (const float*)d_in[3];
    const float* w_down   = (const float*)d_in[4];
    float* out = (float*)d_out;

    cudaFuncSetAttribute(gateup_bf16, cudaFuncAttributeMaxDynamicSharedMemorySize, GU_DYN);
    cudaFuncSetAttribute(down_bf16,   cudaFuncAttributeMaxDynamicSharedMemorySize, DN_DYN);

    prep_x_wd<<<XC_BLOCKS + 1024, 256>>>(x, w_down);            // x split + wd split + zero
    prep_wgu<<<dim3(EHDIM / 32, DMODEL / 64), dim3(32, 8)>>>(w_gate, w_up);
    router_kernel<<<NTOK / 8, 256>>>(x, w_router);
    gateup_bf16<<<dim3(NTOK / 128, HDIM / 64, NEXP), 256, GU_DYN>>>();
    convert_part<<<(NTOK * HDIM / 4) / 256, 256>>>();
    down_bf16<<<dim3(NTOK / 128, DMODEL / 64), 256, DN_DYN>>>(out, out + (out_size - 1));
}

// round 17
// speedup vs baseline: 1.4867x; 1.4867x over previous
#include <cuda_runtime.h>
#include <cuda_bf16.h>
#include <math.h>
#include <stdint.h>

#define NTOK 4096
#define DMODEL 512
#define NEXP 8
#define HDIM 2048
#define EHDIM (NEXP * HDIM)   // 16384

// ---------------- device scratch ----------------
__device__ __align__(16) unsigned short g_xh[NTOK * DMODEL];
__device__ __align__(16) unsigned short g_xl[NTOK * DMODEL];
__device__ __align__(16) unsigned short g_wgh[EHDIM * DMODEL];   // [EH][D] transposed
__device__ __align__(16) unsigned short g_wgl[EHDIM * DMODEL];
__device__ __align__(16) unsigned short g_wuh[EHDIM * DMODEL];
__device__ __align__(16) unsigned short g_wul[EHDIM * DMODEL];
__device__ __align__(16) unsigned short g_wdh[DMODEL * HDIM];    // [D][H] transposed
__device__ __align__(16) unsigned short g_wdl[DMODEL * HDIM];
__device__ __align__(16) float  g_part[2 * NTOK * HDIM];
__device__ __align__(16) unsigned short g_ah[NTOK * HDIM];       // summed combined, split
__device__ __align__(16) unsigned short g_al[NTOK * HDIM];
__device__ int    g_cnt[NEXP];
__device__ double g_esum[NEXP];
__device__ int    g_elist[NEXP * NTOK];   // token | (slot<<16)
__device__ float  g_eprob[NEXP * NTOK];

// ---------------- helpers ----------------
__device__ __forceinline__ uint32_t smem_u32(const void* p) {
    uint32_t a;
    asm("{ .reg .u64 t; cvta.to.shared.u64 t, %1; cvt.u32.u64 %0, t; }"
        : "=r"(a) : "l"(p));
    return a;
}
__device__ __forceinline__ void cp16(uint32_t dst, const void* src) {
    asm volatile("cp.async.cg.shared.global [%0], [%1], 16;" :: "r"(dst), "l"(src));
}
#define CP_COMMIT() asm volatile("cp.async.commit_group;" ::: "memory")
#define CP_WAIT1()  asm volatile("cp.async.wait_group 1;" ::: "memory")

__device__ __forceinline__ void ldm4(uint32_t* r, uint32_t addr) {
    asm volatile("ldmatrix.sync.aligned.m8n8.x4.shared.b16 {%0,%1,%2,%3}, [%4];"
                 : "=r"(r[0]), "=r"(r[1]), "=r"(r[2]), "=r"(r[3]) : "r"(addr));
}

// m16n8k16 bf16 MMA (sm_80 baseline PTX -> tensor pipe)
__device__ __forceinline__ void mma16(float* c, const uint32_t* a, const uint32_t* b) {
    asm volatile(
        "mma.sync.aligned.m16n8k16.row.col.f32.bf16.bf16.f32 "
        "{%0,%1,%2,%3}, {%4,%5,%6,%7}, {%8,%9}, {%0,%1,%2,%3};"
        : "+f"(c[0]), "+f"(c[1]), "+f"(c[2]), "+f"(c[3])
        : "r"(a[0]), "r"(a[1]), "r"(a[2]), "r"(a[3]), "r"(b[0]), "r"(b[1]));
}

__device__ __forceinline__ void bsplit(float v, unsigned short& h, unsigned short& l) {
    __nv_bfloat16 hb = __float2bfloat16(v);
    h = __bfloat16_as_ushort(hb);
    float r = v - __bfloat162float(hb);
    l = __bfloat16_as_ushort(__float2bfloat16(r));
}

// ---------------- merged prep: x split + w_down split-transpose ----------------
// blocks [0, 2048): prep_xc (256 thr linear); blocks [2048, 3072): prep_wd (32x8 logic)
#define XC_BLOCKS 2048
__global__ void prep_x_wd(const float* __restrict__ x, const float* __restrict__ wd) {
    if (blockIdx.x < XC_BLOCKS) {
        int i = blockIdx.x * 256 + threadIdx.x;
        if (i == 0) {
#pragma unroll
            for (int e = 0; e < NEXP; e++) { g_cnt[e] = 0; g_esum[e] = 0.0; }
        }
        float4 v = reinterpret_cast<const float4*>(x)[i];
        unsigned short h0, h1, h2, h3, l0, l1, l2, l3;
        bsplit(v.x, h0, l0); bsplit(v.y, h1, l1);
        bsplit(v.z, h2, l2); bsplit(v.w, h3, l3);
        reinterpret_cast<ushort4*>(g_xh)[i] = make_ushort4(h0, h1, h2, h3);
        reinterpret_cast<ushort4*>(g_xl)[i] = make_ushort4(l0, l1, l2, l3);
    } else {
        __shared__ float t[32][33];
        int b = blockIdx.x - XC_BLOCKS;             // 0..1023
        int db = (b & 15) * 32, hb = (b >> 4) * 32; // 16 d-tiles x 64 h-tiles
        int tx = threadIdx.x & 31, ty = threadIdx.x >> 5;
#pragma unroll
        for (int i = 0; i < 4; i++) {
            t[ty + i * 8][tx] = wd[(size_t)(hb + ty + i * 8) * DMODEL + db + tx];
        }
        __syncthreads();
#pragma unroll
        for (int i = 0; i < 4; i++) {
            size_t o = (size_t)(db + ty + i * 8) * HDIM + hb + tx;
            unsigned short hh, ll;
            bsplit(t[tx][ty + i * 8], hh, ll);
            g_wdh[o] = hh; g_wdl[o] = ll;
        }
    }
}

// 64(d) x 32(h) tiles; ushort2 stores -> full 128B/warp write transactions
__global__ void prep_wgu(const float* __restrict__ wg, const float* __restrict__ wu) {
    __shared__ float tg[64][33], tu[64][33];
    int hb = blockIdx.x * 32, db = blockIdx.y * 64;
    int tx = threadIdx.x, ty = threadIdx.y;   // (32, 8)
#pragma unroll
    for (int i = 0; i < 8; i++) {
        int d = db + ty + i * 8;
        tg[ty + i * 8][tx] = wg[(size_t)d * EHDIM + hb + tx];
        tu[ty + i * 8][tx] = wu[(size_t)d * EHDIM + hb + tx];
    }
    __syncthreads();
#pragma unroll
    for (int i = 0; i < 4; i++) {
        int hh = ty + i * 8;
        size_t o = (size_t)(hb + hh) * DMODEL + db + tx * 2;
        unsigned short a0, b0, a1, b1;
        bsplit(tg[tx * 2][hh], a0, b0); bsplit(tg[tx * 2 + 1][hh], a1, b1);
        *reinterpret_cast<ushort2*>(&g_wgh[o]) = make_ushort2(a0, a1);
        *reinterpret_cast<ushort2*>(&g_wgl[o]) = make_ushort2(b0, b1);
        bsplit(tu[tx * 2][hh], a0, b0); bsplit(tu[tx * 2 + 1][hh], a1, b1);
        *reinterpret_cast<ushort2*>(&g_wuh[o]) = make_ushort2(a0, a1);
        *reinterpret_cast<ushort2*>(&g_wul[o]) = make_ushort2(b0, b1);
    }
}

// sum the two expert partials, bf16-split -> A operand of down GEMM
__global__ void convert_part() {
    int i = blockIdx.x * blockDim.x + threadIdx.x;   // over NTOK*HDIM/4
    float4 a = reinterpret_cast<const float4*>(g_part)[i];
    float4 b = reinterpret_cast<const float4*>(g_part + (size_t)NTOK * HDIM)[i];
    unsigned short h0, h1, h2, h3, l0, l1, l2, l3;
    bsplit(a.x + b.x, h0, l0); bsplit(a.y + b.y, h1, l1);
    bsplit(a.z + b.z, h2, l2); bsplit(a.w + b.w, h3, l3);
    reinterpret_cast<ushort4*>(g_ah)[i] = make_ushort4(h0, h1, h2, h3);
    reinterpret_cast<ushort4*>(g_al)[i] = make_ushort4(l0, l1, l2, l3);
}

// ---------------- router: one warp per token ----------------
__global__ void router_kernel(const float* __restrict__ x,
                              const float* __restrict__ w_router) {
    int warp = (blockIdx.x * blockDim.x + threadIdx.x) >> 5;
    int lane = threadIdx.x & 31;
    if (warp >= NTOK) return;
    int n = warp;

    float acc[NEXP];
#pragma unroll
    for (int e = 0; e < NEXP; e++) acc[e] = 0.f;
    const float* xr = x + (size_t)n * DMODEL;
    for (int d = lane; d < DMODEL; d += 32) {
        float xv = xr[d];
        const float* w = w_router + d * NEXP;
#pragma unroll
        for (int e = 0; e < NEXP; e++) acc[e] += xv * w[e];
    }
#pragma unroll
    for (int off = 16; off > 0; off >>= 1)
#pragma unroll
        for (int e = 0; e < NEXP; e++)
            acc[e] += __shfl_xor_sync(0xFFFFFFFFu, acc[e], off);

    if (lane == 0) {
        float mx = acc[0];
#pragma unroll
        for (int e = 1; e < NEXP; e++) mx = fmaxf(mx, acc[e]);
        float s = 0.f, probs[NEXP];
#pragma unroll
        for (int e = 0; e < NEXP; e++) { probs[e] = expf(acc[e] - mx); s += probs[e]; }
        float inv = 1.f / s;
#pragma unroll
        for (int e = 0; e < NEXP; e++) {
            probs[e] *= inv;
            atomicAdd(&g_esum[e], (double)probs[e]);
        }
        int i1 = 0;
#pragma unroll
        for (int e = 1; e < NEXP; e++) if (probs[e] > probs[i1]) i1 = e;
        int i2 = (i1 == 0) ? 1 : 0;
#pragma unroll
        for (int e = 0; e < NEXP; e++)
            if (e != i1 && probs[e] > probs[i2]) i2 = e;

        float p1 = probs[i1], p2 = probs[i2];
        float rn = 1.f / (p1 + p2 + 1e-10f);
        int pos1 = atomicAdd(&g_cnt[i1], 1);
        g_elist[i1 * NTOK + pos1] = n;                // slot 0
        g_eprob[i1 * NTOK + pos1] = p1 * rn;
        int pos2 = atomicAdd(&g_cnt[i2], 1);
        g_elist[i2 * NTOK + pos2] = n | (1 << 16);    // slot 1
        g_eprob[i2 * NTOK + pos2] = p2 * rn;
    }
}

// ---------------- gate/up split-bf16 GEMM (3-stage, k16) ----------------
// 256 threads = 8 warps (wm 0..3 x wn 0..1). BM=128 tokens, BN=64 h (dual G,U).
// smem row = [hi 32B (k16) | lo 32B | pad 16B] stride 80B.
#define GQS 80
#define GSTG 20480                       // X(128*80=10240) + G(5120) + U(5120)
#define GU_X(s) ((s) * GSTG)
#define GU_G(s) ((s) * GSTG + 10240)
#define GU_U(s) ((s) * GSTG + 15360)
#define GU_META (3 * GSTG)               // 61440
#define GU_DYN  (GU_META + 1664)

__global__ __launch_bounds__(256, 2) void gateup_bf16() {
    extern __shared__ __align__(16) char smem[];
    uint32_t sb = smem_u32(smem);
    float*  sP   = reinterpret_cast<float*>(smem + GU_META);          // 128 floats
    float** sDst = reinterpret_cast<float**>(smem + GU_META + 512);   // 128 ptrs

    const int tid = threadIdx.x;
    const int e = blockIdx.z;
    const int cnt = g_cnt[e];
    const int row0 = blockIdx.x * 128;
    if (row0 >= cnt) return;
    const int h0 = blockIdx.y * 64;

    if (tid < 128) {
        int gr = row0 + tid;
        bool valid = gr < cnt;
        int ent = valid ? g_elist[e * NTOK + gr] : 0;
        int t = ent & 0xFFFF;
        int slot = (ent >> 16) & 1;
        sP[tid] = valid ? g_eprob[e * NTOK + gr] : 0.f;
        sDst[tid] = valid ? (g_part + ((size_t)slot * NTOK + t) * HDIM + h0) : (float*)0;
    }

    // cp.async: every thread does 4 ops/chunk: X rows r and r+64, G row r, U row r
    const int q = tid & 3, hilo = q >> 1, seg = q & 1;
    const int r = tid >> 2;                 // 0..63
    const unsigned short* xsrc0;
    const unsigned short* xsrc1;
    {
        int gr0 = row0 + r;
        int gr1 = row0 + r + 64;
        int e0 = (gr0 < cnt) ? g_elist[e * NTOK + gr0] : 0;
        int e1 = (gr1 < cnt) ? g_elist[e * NTOK + gr1] : 0;
        const unsigned short* base = hilo ? g_xl : g_xh;
        xsrc0 = base + (size_t)(e0 & 0xFFFF) * DMODEL + seg * 8;
        xsrc1 = base + (size_t)(e1 & 0xFFFF) * DMODEL + seg * 8;
    }
    const unsigned short* gsrc;
    const unsigned short* usrc;
    {
        size_t ro = (size_t)(e * HDIM + h0 + r) * DMODEL + seg * 8;
        gsrc = (hilo ? g_wgl : g_wgh) + ro;
        usrc = (hilo ? g_wul : g_wuh) + ro;
    }
    const uint32_t xoff0 = (uint32_t)r * GQS + hilo * 32 + seg * 16;
    const uint32_t xoff1 = (uint32_t)(r + 64) * GQS + hilo * 32 + seg * 16;
    const uint32_t woff  = (uint32_t)r * GQS + hilo * 32 + seg * 16;

    // fragment addressing (verified R6/R10/R11 mapping)
    const int warp = tid >> 5, lane = tid & 31;
    const int wm = warp & 3, wn = warp >> 2;   // wm 0..3, wn 0..1
    const int grp = lane >> 2, tig = lane & 3;
    const uint32_t aLane = (uint32_t)(((lane & 7) + (lane & 8)) * GQS + ((lane & 16) ? 16 : 0));
    const uint32_t bLane = (uint32_t)((((lane & 7) + ((lane & 16) >> 1)) * GQS) + ((lane & 8) ? 16 : 0));
    uint32_t aBase[2], bBase[2];
#pragma unroll
    for (int mt = 0; mt < 2; mt++) aBase[mt] = (uint32_t)(wm * 32 + mt * 16) * GQS + aLane;
#pragma unroll
    for (int bh = 0; bh < 2; bh++) bBase[bh] = (uint32_t)(wn * 32 + bh * 16) * GQS + bLane;

    float accG[2][4][4], accU[2][4][4];   // [mt][bh*2+nt][4]
#pragma unroll
    for (int mt = 0; mt < 2; mt++)
#pragma unroll
        for (int j = 0; j < 4; j++)
#pragma unroll
            for (int k = 0; k < 4; k++) { accG[mt][j][k] = 0.f; accU[mt][j][k] = 0.f; }

    // prologue: stages 0,1
#pragma unroll
    for (int c = 0; c < 2; c++) {
        cp16(sb + GU_X(c) + xoff0, xsrc0 + c * 16);
        cp16(sb + GU_X(c) + xoff1, xsrc1 + c * 16);
        cp16(sb + GU_G(c) + woff, gsrc + c * 16);
        cp16(sb + GU_U(c) + woff, usrc + c * 16);
        CP_COMMIT();
    }

    const int NCH = DMODEL / 16;   // 32
    for (int c = 0; c < NCH; c++) {
        int s = c % 3;
        CP_WAIT1();
        __syncthreads();
        if (c + 2 < NCH) {
            int s2 = (c + 2) % 3;
            int k0 = (c + 2) * 16;
            cp16(sb + GU_X(s2) + xoff0, xsrc0 + k0);
            cp16(sb + GU_X(s2) + xoff1, xsrc1 + k0);
            cp16(sb + GU_G(s2) + woff, gsrc + k0);
            cp16(sb + GU_U(s2) + woff, usrc + k0);
        }
        CP_COMMIT();   // uniform group counting

        uint32_t xb = sb + GU_X(s), gb = sb + GU_G(s), ub = sb + GU_U(s);
        uint32_t ah[2][4], al[2][4];
        ldm4(ah[0], xb + aBase[0]); ldm4(al[0], xb + aBase[0] + 32);
        ldm4(ah[1], xb + aBase[1]); ldm4(al[1], xb + aBase[1] + 32);
        {
            uint32_t bH[2][4], bL[2][4];
            ldm4(bH[0], gb + bBase[0]); ldm4(bL[0], gb + bBase[0] + 32);
            ldm4(bH[1], gb + bBase[1]); ldm4(bL[1], gb + bBase[1] + 32);
#pragma unroll
            for (int mt = 0; mt < 2; mt++)
#pragma unroll
                for (int bh = 0; bh < 2; bh++)
#pragma unroll
                    for (int nt = 0; nt < 2; nt++) {
                        float* acc = accG[mt][bh * 2 + nt];
                        mma16(acc, ah[mt], bH[bh] + nt * 2);
                        mma16(acc, ah[mt], bL[bh] + nt * 2);
                        mma16(acc, al[mt], bH[bh] + nt * 2);
                    }
        }
        {
            uint32_t bH[2][4], bL[2][4];
            ldm4(bH[0], ub + bBase[0]); ldm4(bL[0], ub + bBase[0] + 32);
            ldm4(bH[1], ub + bBase[1]); ldm4(bL[1], ub + bBase[1] + 32);
#pragma unroll
            for (int mt = 0; mt < 2; mt++)
#pragma unroll
                for (int bh = 0; bh < 2; bh++)
#pragma unroll
                    for (int nt = 0; nt < 2; nt++) {
                        float* acc = accU[mt][bh * 2 + nt];
                        mma16(acc, ah[mt], bH[bh] + nt * 2);
                        mma16(acc, ah[mt], bL[bh] + nt * 2);
                        mma16(acc, al[mt], bH[bh] + nt * 2);
                    }
        }
    }

    // epilogue: p * silu(g) * u
#pragma unroll
    for (int mt = 0; mt < 2; mt++) {
        int r0 = wm * 32 + mt * 16 + grp;
        int r1 = r0 + 8;
        float p0 = sP[r0], p1 = sP[r1];
        float* d0 = sDst[r0];
        float* d1 = sDst[r1];
#pragma unroll
        for (int bh = 0; bh < 2; bh++)
#pragma unroll
            for (int nt = 0; nt < 2; nt++) {
                int co = wn * 32 + bh * 16 + nt * 8 + tig * 2;
                const float* aG = accG[mt][bh * 2 + nt];
                const float* aU = accU[mt][bh * 2 + nt];
                if (d0) {
                    float g0 = aG[0], u0 = aU[0];
                    float g1 = aG[1], u1 = aU[1];
                    float2 v;
                    v.x = p0 * (g0 / (1.f + __expf(-g0))) * u0;
                    v.y = p0 * (g1 / (1.f + __expf(-g1))) * u1;
                    *reinterpret_cast<float2*>(d0 + co) = v;
                }
                if (d1) {
                    float g2 = aG[2], u2 = aU[2];
                    float g3 = aG[3], u3 = aU[3];
                    float2 v;
                    v.x = p1 * (g2 / (1.f + __expf(-g2))) * u2;
                    v.y = p1 * (g3 / (1.f + __expf(-g3))) * u3;
                    *reinterpret_cast<float2*>(d1 + co) = v;
                }
            }
    }
}

// ---------------- down split-bf16 GEMM (3-stage, k16 + fused lbloss) ----------------
// 256 threads = 8 warps (wm4 x wn2). BM=128 tokens, BN=64 d-cols, K=2048.
#define DSTG 15360
#define DN_A(s) ((s) * DSTG)
#define DN_B(s) ((s) * DSTG + 10240)
#define DN_DYN  (3 * DSTG)               // 46080

__global__ __launch_bounds__(256, 2) void down_bf16(float* __restrict__ out,
                                                    float* __restrict__ out_scalar) {
    extern __shared__ __align__(16) char smem[];
    uint32_t sb = smem_u32(smem);

    const int tid = threadIdx.x;
    const int row0 = blockIdx.x * 128;
    const int c0 = blockIdx.y * 64;

    // fused lb-loss (esum final since router; disjoint output element)
    if (blockIdx.x == 0 && blockIdx.y == 0 && tid == 0) {
        double lb = 0.0;
#pragma unroll
        for (int e = 0; e < NEXP; e++) {
            double m = g_esum[e] / (double)NTOK;
            lb += m * log(m * (double)NEXP + 1e-10);
        }
        out_scalar[0] = (float)((double)NEXP * lb);
    }

    const int q = tid & 3, hilo = q >> 1, seg = q & 1;
    const int r = tid >> 2;                 // 0..63
    const unsigned short* abase = hilo ? g_al : g_ah;
    const unsigned short* asrc0 = abase + (size_t)(row0 + r) * HDIM + seg * 8;
    const unsigned short* asrc1 = abase + (size_t)(row0 + r + 64) * HDIM + seg * 8;
    const unsigned short* bsrc =
        (hilo ? g_wdl : g_wdh) + (size_t)(c0 + r) * HDIM + seg * 8;
    const uint32_t aoff0 = (uint32_t)r * GQS + hilo * 32 + seg * 16;
    const uint32_t aoff1 = (uint32_t)(r + 64) * GQS + hilo * 32 + seg * 16;
    const uint32_t boff  = (uint32_t)r * GQS + hilo * 32 + seg * 16;

    const int warp = tid >> 5, lane = tid & 31;
    const int wm = warp & 3, wn = warp >> 2;
    const int grp = lane >> 2, tig = lane & 3;
    const uint32_t aLane = (uint32_t)(((lane & 7) + (lane & 8)) * GQS + ((lane & 16) ? 16 : 0));
    const uint32_t bLane = (uint32_t)((((lane & 7) + ((lane & 16) >> 1)) * GQS) + ((lane & 8) ? 16 : 0));
    uint32_t aBase[2], bBase[2];
#pragma unroll
    for (int mt = 0; mt < 2; mt++) aBase[mt] = (uint32_t)(wm * 32 + mt * 16) * GQS + aLane;
#pragma unroll
    for (int bh = 0; bh < 2; bh++) bBase[bh] = (uint32_t)(wn * 32 + bh * 16) * GQS + bLane;

    float acc[2][4][4];
#pragma unroll
    for (int mt = 0; mt < 2; mt++)
#pragma unroll
        for (int j = 0; j < 4; j++)
#pragma unroll
            for (int k = 0; k < 4; k++) acc[mt][j][k] = 0.f;

#pragma unroll
    for (int c = 0; c < 2; c++) {
        int k0 = c * 16;
        cp16(sb + DN_A(c) + aoff0, asrc0 + k0);
        cp16(sb + DN_A(c) + aoff1, asrc1 + k0);
        cp16(sb + DN_B(c) + boff,  bsrc + k0);
        CP_COMMIT();
    }

    const int NCH = HDIM / 16;   // 128
    for (int c = 0; c < NCH; c++) {
        int s = c % 3;
        CP_WAIT1();
        __syncthreads();
        if (c + 2 < NCH) {
            int s2 = (c + 2) % 3;
            int k0 = (c + 2) * 16;
            cp16(sb + DN_A(s2) + aoff0, asrc0 + k0);
            cp16(sb + DN_A(s2) + aoff1, asrc1 + k0);
            cp16(sb + DN_B(s2) + boff,  bsrc + k0);
        }
        CP_COMMIT();

        uint32_t ab = sb + DN_A(s), bb = sb + DN_B(s);
        uint32_t ah[2][4], al[2][4], bH[2][4], bL[2][4];
        ldm4(ah[0], ab + aBase[0]); ldm4(al[0], ab + aBase[0] + 32);
        ldm4(ah[1], ab + aBase[1]); ldm4(al[1], ab + aBase[1] + 32);
        ldm4(bH[0], bb + bBase[0]); ldm4(bL[0], bb + bBase[0] + 32);
        ldm4(bH[1], bb + bBase[1]); ldm4(bL[1], bb + bBase[1] + 32);

#pragma unroll
        for (int mt = 0; mt < 2; mt++)
#pragma unroll
            for (int bh = 0; bh < 2; bh++)
#pragma unroll
                for (int nt = 0; nt < 2; nt++) {
                    float* a = acc[mt][bh * 2 + nt];
                    mma16(a, ah[mt], bH[bh] + nt * 2);
                    mma16(a, ah[mt], bL[bh] + nt * 2);
                    mma16(a, al[mt], bH[bh] + nt * 2);
                }
    }

    // epilogue
#pragma unroll
    for (int mt = 0; mt < 2; mt++) {
        int r0 = row0 + wm * 32 + mt * 16 + grp;
        int r1 = r0 + 8;
#pragma unroll
        for (int bh = 0; bh < 2; bh++)
#pragma unroll
            for (int nt = 0; nt < 2; nt++) {
                int co = c0 + wn * 32 + bh * 16 + nt * 8 + tig * 2;
                const float* a = acc[mt][bh * 2 + nt];
                *reinterpret_cast<float2*>(out + (size_t)r0 * DMODEL + co) =
                    make_float2(a[0], a[1]);
                *reinterpret_cast<float2*>(out + (size_t)r1 * DMODEL + co) =
                    make_float2(a[2], a[3]);
            }
    }
}

// ---------------- launch ----------------
extern "C" void kernel_launch(void* const* d_in, const int* in_sizes, int n_in,
                              void* d_out, int out_size) {
    const float* x        = (const float*)d_in[0];
    const float* w_router = (const float*)d_in[1];
    const float* w_gate   = (const float*)d_in[2];
    const float* w_up     = (const float*)d_in[3];
    const float* w_down   = (const float*)d_in[4];
    float* out = (float*)d_out;

    cudaFuncSetAttribute(gateup_bf16, cudaFuncAttributeMaxDynamicSharedMemorySize, GU_DYN);
    cudaFuncSetAttribute(down_bf16,   cudaFuncAttributeMaxDynamicSharedMemorySize, DN_DYN);

    prep_x_wd<<<XC_BLOCKS + 1024, 256>>>(x, w_down);            // x split + wd split + zero
    prep_wgu<<<dim3(EHDIM / 32, DMODEL / 64), dim3(32, 8)>>>(w_gate, w_up);
    router_kernel<<<NTOK / 8, 256>>>(x, w_router);
    gateup_bf16<<<dim3(NTOK / 128, HDIM / 64, NEXP), 256, GU_DYN>>>();
    convert_part<<<(NTOK * HDIM / 4) / 256, 256>>>();
    down_bf16<<<dim3(NTOK / 128, DMODEL / 64), 256, DN_DYN>>>(out, out + (out_size - 1));
}